// round 4
// baseline (speedup 1.0000x reference)
#include <cuda_runtime.h>
#include <cuda_fp16.h>
#include <cstdint>

// Problem constants
#define E_    8
#define K_    2048
#define N_    2048
#define T_    1024
#define TOPK_ 2
#define NPAIR (T_ * TOPK_)      // 2048 token-expert pairs

// GEMM tiling
#define BM 128
#define BN 128
#define BK 64
#define LDA (BK + 8)            // 72 halfs  (pad kills ldmatrix bank conflicts)
#define LDB (BN + 8)            // 136 halfs
#define MAX_TILES 32

// ---------------- scratch (static device memory; no allocation) ----------------
__device__ __align__(128) __half g_A[(NPAIR + BM) * K_];   // ~8.9 MB, pad rows never stored
__device__ __align__(128) float  g_C[(size_t)NPAIR * N_];  // 16 MB
__device__ float g_bias[NPAIR + BM];
__device__ float g_srow[E_ * K_];
__device__ float g_zrow[E_ * K_];
__device__ int   g_pair_token[NPAIR];
__device__ int   g_pair_expert[NPAIR];
__device__ int   g_pos[NPAIR];             // (t*TOPK+j) -> slot
__device__ int   g_tile_start[MAX_TILES];
__device__ int   g_tile_cnt[MAX_TILES];
__device__ int   g_tile_exp[MAX_TILES];
__device__ int   g_num_tiles;

// ---------------- PTX helpers ----------------
__device__ __forceinline__ uint32_t smem_u32(const void* p) {
    return (uint32_t)__cvta_generic_to_shared(p);
}
__device__ __forceinline__ void ldsm_x4(uint32_t* r, const void* p) {
    uint32_t a = smem_u32(p);
    asm volatile("ldmatrix.sync.aligned.m8n8.x4.shared.b16 {%0,%1,%2,%3}, [%4];"
                 : "=r"(r[0]), "=r"(r[1]), "=r"(r[2]), "=r"(r[3]) : "r"(a));
}
__device__ __forceinline__ void ldsm_x2t(uint32_t* r, const void* p) {
    uint32_t a = smem_u32(p);
    asm volatile("ldmatrix.sync.aligned.m8n8.x2.trans.shared.b16 {%0,%1}, [%2];"
                 : "=r"(r[0]), "=r"(r[1]) : "r"(a));
}
__device__ __forceinline__ void mma16816(float* c, const uint32_t* a, const uint32_t* b) {
    asm volatile("mma.sync.aligned.m16n8k16.row.col.f32.f16.f16.f32 "
                 "{%0,%1,%2,%3}, {%4,%5,%6,%7}, {%8,%9}, {%0,%1,%2,%3};"
                 : "+f"(c[0]), "+f"(c[1]), "+f"(c[2]), "+f"(c[3])
                 : "r"(a[0]), "r"(a[1]), "r"(a[2]), "r"(a[3]),
                   "r"(b[0]), "r"(b[1]));
}
__device__ __forceinline__ void cp_async16(void* dst, const void* src) {
    uint32_t d = smem_u32(dst);
    asm volatile("cp.async.cg.shared.global [%0], [%1], 16;" :: "r"(d), "l"(src));
}
__device__ __forceinline__ void cp_commit()  { asm volatile("cp.async.commit_group;"); }
__device__ __forceinline__ void cp_wait0()   { asm volatile("cp.async.wait_group 0;" ::: "memory"); }

// ---------------- kernel 1: gather per-(e,k) scale/zero rows ----------------
__global__ void k_sz(const float* __restrict__ scales, const float* __restrict__ zeros) {
    int idx = blockIdx.x * blockDim.x + threadIdx.x;     // over E*K
    if (idx >= E_ * K_) return;
    int e = idx / K_;
    int k = idx - e * K_;
    int g = k >> 7;                                       // k / GROUP_SIZE(128)
    size_t off = (size_t)e * K_ * (K_ / 128) + (size_t)k * (K_ / 128) + g;
    g_srow[idx] = scales[off];
    g_zrow[idx] = zeros[off];
}

// ---------------- kernel 2: route (counting sort by expert + tile table) ----------------
__global__ void k_route(const int* __restrict__ topk_ids) {
    __shared__ int cnt[E_], cur[E_];
    int tid = threadIdx.x;                                // 1024 threads
    if (tid < E_) cnt[tid] = 0;
    __syncthreads();
    for (int i = tid; i < NPAIR; i += blockDim.x)
        atomicAdd(&cnt[topk_ids[i]], 1);
    __syncthreads();
    if (tid == 0) {
        int acc = 0, nt = 0;
        for (int e = 0; e < E_; e++) {
            cur[e] = acc;
            int c = cnt[e];
            for (int m0 = 0; m0 < c; m0 += BM) {
                g_tile_start[nt] = acc + m0;
                g_tile_cnt[nt]   = min(BM, c - m0);
                g_tile_exp[nt]   = e;
                nt++;
            }
            acc += c;
        }
        g_num_tiles = nt;
    }
    __syncthreads();
    for (int i = tid; i < NPAIR; i += blockDim.x) {
        int e = topk_ids[i];
        int slot = atomicAdd(&cur[e], 1);
        g_pair_token[slot]  = i / TOPK_;
        g_pair_expert[slot] = e;
        g_pos[i] = slot;
    }
}

// ---------------- kernel 3: build A rows (x*s in fp16) + bias (x.z) ----------------
__global__ void k_prepA(const float* __restrict__ x) {
    int slot = blockIdx.x;
    int t = g_pair_token[slot];
    int e = g_pair_expert[slot];
    const float* xr = x + (size_t)t * K_;
    const float* sr = g_srow + (size_t)e * K_;
    const float* zr = g_zrow + (size_t)e * K_;
    __half* ar = g_A + (size_t)slot * K_;
    float b = 0.f;
    for (int k = threadIdx.x; k < K_; k += blockDim.x) {
        float xv = xr[k];
        ar[k] = __float2half_rn(xv * sr[k]);
        b += xv * zr[k];
    }
    // block reduce (256 threads = 8 warps)
    __shared__ float red[8];
    #pragma unroll
    for (int o = 16; o; o >>= 1) b += __shfl_xor_sync(0xffffffffu, b, o);
    if ((threadIdx.x & 31) == 0) red[threadIdx.x >> 5] = b;
    __syncthreads();
    if (threadIdx.x < 8) {
        b = red[threadIdx.x];
        #pragma unroll
        for (int o = 4; o; o >>= 1) b += __shfl_xor_sync(0xffu, b, o);
        if (threadIdx.x == 0) g_bias[slot] = b;
    }
}

// ---------------- kernel 4: grouped GEMM  C[pair,n] = A[pair,:] . Wq[e,:,n] ----------------
// Software-pipelined: B tile k0+1 is LDG-prefetched into registers while
// tile k0 is being converted/computed, hiding the ~600-cycle DRAM latency
// under the MMA phase.
__global__ __launch_bounds__(256) void k_gemm(const int* __restrict__ w_q) {
    int tile = blockIdx.y;
    if (tile >= g_num_tiles) return;
    const int n0     = blockIdx.x * BN;
    const int pstart = g_tile_start[tile];
    const int mcnt   = g_tile_cnt[tile];
    const int e      = g_tile_exp[tile];

    __shared__ __align__(16) __half sA[BM * LDA];
    __shared__ __align__(16) __half sB[BK * LDB];

    const int tid  = threadIdx.x;
    const int lane = tid & 31;
    const int warp = tid >> 5;
    const int wm   = warp & 1;        // 2 warps along M (64 rows each)
    const int wn   = warp >> 1;       // 4 warps along N (32 cols each)

    float acc[4][4][4];
    #pragma unroll
    for (int i = 0; i < 4; i++)
        #pragma unroll
        for (int j = 0; j < 4; j++)
            #pragma unroll
            for (int v = 0; v < 4; v++) acc[i][j][v] = 0.f;

    const int*    Bg = w_q + (size_t)e * K_ * N_ + n0;
    const __half* Ag = g_A + (size_t)pstart * K_;

    // B prefetch registers: 8 int4 chunks per thread = one BKxBN tile per CTA
    const int br  = tid >> 5;         // base row in tile (stride 8 over i)
    const int bc4 = tid & 31;         // int4-column
    int4 breg[8];
    #pragma unroll
    for (int i = 0; i < 8; i++)
        breg[i] = *(const int4*)(Bg + (size_t)(br + i * 8) * N_ + bc4 * 4);

    for (int k0 = 0; k0 < K_; k0 += BK) {
        // ---- A tile via cp.async first (in flight during B convert) ----
        #pragma unroll
        for (int i = 0; i < 4; i++) {
            int cid = tid + i * 256;          // 1024 chunks (8 per row)
            int r   = cid >> 3;
            int c   = cid & 7;
            cp_async16(&sA[r * LDA + c * 8], Ag + (size_t)r * K_ + k0 + c * 8);
        }
        cp_commit();

        // ---- convert prefetched B regs -> fp16 smem (exact: values 0..255) ----
        #pragma unroll
        for (int i = 0; i < 8; i++) {
            int r = br + i * 8;
            __half2 h01 = __halves2half2(__float2half_rn((float)breg[i].x),
                                         __float2half_rn((float)breg[i].y));
            __half2 h23 = __halves2half2(__float2half_rn((float)breg[i].z),
                                         __float2half_rn((float)breg[i].w));
            __half2* dst = (__half2*)&sB[r * LDB + bc4 * 4];
            dst[0] = h01;
            dst[1] = h23;
        }

        // ---- prefetch next B tile (latency hidden under compute below) ----
        if (k0 + BK < K_) {
            const int* Bn = Bg + (size_t)(k0 + BK) * N_;
            #pragma unroll
            for (int i = 0; i < 8; i++)
                breg[i] = *(const int4*)(Bn + (size_t)(br + i * 8) * N_ + bc4 * 4);
        }

        cp_wait0();
        __syncthreads();

        // ---- compute ----
        #pragma unroll
        for (int kk = 0; kk < BK; kk += 16) {
            uint32_t af[4][4];
            #pragma unroll
            for (int mi = 0; mi < 4; mi++) {
                int row = wm * 64 + mi * 16 + (lane & 15);
                int col = kk + 8 * (lane >> 4);
                ldsm_x4(af[mi], &sA[row * LDA + col]);
            }
            uint32_t bf[4][2];
            #pragma unroll
            for (int ni = 0; ni < 4; ni++) {
                int row = kk + (lane & 15);
                int col = wn * 32 + ni * 8;
                ldsm_x2t(bf[ni], &sB[row * LDB + col]);
            }
            #pragma unroll
            for (int mi = 0; mi < 4; mi++)
                #pragma unroll
                for (int ni = 0; ni < 4; ni++)
                    mma16816(acc[mi][ni], af[mi], bf[ni]);
        }
        __syncthreads();
    }

    // ---- store C (fp32 scratch), guard partial M ----
    float* Cg = g_C + (size_t)pstart * N_ + n0;
    #pragma unroll
    for (int mi = 0; mi < 4; mi++) {
        int r0 = wm * 64 + mi * 16 + (lane >> 2);
        #pragma unroll
        for (int ni = 0; ni < 4; ni++) {
            int c = wn * 32 + ni * 8 + (lane & 3) * 2;
            if (r0 < mcnt)
                *(float2*)&Cg[(size_t)r0 * N_ + c] =
                    make_float2(acc[mi][ni][0], acc[mi][ni][1]);
            if (r0 + 8 < mcnt)
                *(float2*)&Cg[(size_t)(r0 + 8) * N_ + c] =
                    make_float2(acc[mi][ni][2], acc[mi][ni][3]);
        }
    }
}

// ---------------- kernel 5: combine  out[t] = sum_j tw * (C[slot] + bias) ----------------
__global__ void k_combine(const float* __restrict__ topk_weights, float* __restrict__ out) {
    int t = blockIdx.x;
    int s0 = g_pos[t * TOPK_ + 0];
    int s1 = g_pos[t * TOPK_ + 1];
    float w0 = topk_weights[t * TOPK_ + 0];
    float w1 = topk_weights[t * TOPK_ + 1];
    float b0 = g_bias[s0];
    float b1 = g_bias[s1];
    const float* c0 = g_C + (size_t)s0 * N_;
    const float* c1 = g_C + (size_t)s1 * N_;
    float* o = out + (size_t)t * N_;
    for (int n = threadIdx.x; n < N_; n += blockDim.x)
        o[n] = w0 * (c0[n] + b0) + w1 * (c1[n] + b1);
}

// ---------------- launch ----------------
extern "C" void kernel_launch(void* const* d_in, const int* in_sizes, int n_in,
                              void* d_out, int out_size) {
    const float* x      = (const float*)d_in[0];
    const int*   w_q    = (const int*)  d_in[1];
    const float* scales = (const float*)d_in[2];
    const float* zeros  = (const float*)d_in[3];
    const float* tw     = (const float*)d_in[4];
    const int*   tids   = (const int*)  d_in[5];
    float* out = (float*)d_out;

    k_sz<<<(E_ * K_ + 255) / 256, 256>>>(scales, zeros);
    k_route<<<1, 1024>>>(tids);
    k_prepA<<<NPAIR, 256>>>(x);
    dim3 gg(N_ / BN, (NPAIR / BM) + E_);   // 16 x 24, extra tiles early-exit
    k_gemm<<<gg, 256>>>(w_q);
    k_combine<<<T_, 256>>>(tw, out);
}